// round 1
// baseline (speedup 1.0000x reference)
#include <cuda_runtime.h>

#define Nn 22
#define NP 24          // padded node dim for float4-aligned SMEM rows
#define Fd 192
#define THREADS 192

// ---- SMEM layout (floats) ----
#define XS_OFF   0        // xs[k][m]: [192][24] transposed x tile
#define WH_OFF   4608     // wh[head][m][n]: [2][22][192]
#define WHO_OFF  WH_OFF   // who[m][n]: [22][192] (aliases wh, used after wh dead)
#define HC_OFF   13056    // hc[k][m]: [384][24] transposed hcat
#define ATT_OFF  22272    // att[3][22][22]
#define EV_OFF   23724    // e vectors: 132
#define ADJ_OFF  23856    // adj [484]
#define AV_OFF   24340    // a1(384) a2(384) ao(384)
#define SMEM_FLOATS 25492
#define SMEM_BYTES (SMEM_FLOATS * 4)

__device__ __forceinline__ void softmax_row(const float esrc, const float* __restrict__ edst,
                                            const float* __restrict__ adjrow,
                                            float* __restrict__ arow)
{
    float vals[Nn];
    float mx = -1e30f;
#pragma unroll
    for (int j = 0; j < Nn; j++) {
        if (adjrow[j] != 0.0f) {
            float v = esrc + edst[j];
            v = (v > 0.0f) ? v : 0.2f * v;   // LeakyReLU(0.2)
            vals[j] = v;
            mx = fmaxf(mx, v);
        } else {
            vals[j] = -1e30f;
        }
    }
    float ssum = 0.0f;
#pragma unroll
    for (int j = 0; j < Nn; j++) {
        float e = (vals[j] > -1e29f) ? expf(vals[j] - mx) : 0.0f;
        arow[j] = e;
        ssum += e;
    }
    float inv = 1.0f / ssum;
#pragma unroll
    for (int j = 0; j < Nn; j++) arow[j] *= inv;
}

__global__ __launch_bounds__(THREADS, 2)
void gat_fused(const float* __restrict__ x, const float* __restrict__ adj,
               const float* __restrict__ W1, const float* __restrict__ a1,
               const float* __restrict__ W2, const float* __restrict__ a2,
               const float* __restrict__ Wo, const float* __restrict__ ao,
               float* __restrict__ out)
{
    extern __shared__ float sm[];
    float* xs   = sm + XS_OFF;
    float* wh   = sm + WH_OFF;
    float* who  = sm + WHO_OFF;
    float* hc   = sm + HC_OFF;
    float* att  = sm + ATT_OFF;
    float* ev   = sm + EV_OFF;
    float* adjs = sm + ADJ_OFF;
    float* avs  = sm + AV_OFF;

    const int t = threadIdx.x;
    const long long b = blockIdx.x;
    const float* xb = x + b * (long long)(Nn * Fd);

    // ---- Phase 0: load x (transposed), adj, a-vectors into SMEM ----
#pragma unroll
    for (int m = 0; m < Nn; m++)
        xs[t * NP + m] = xb[m * Fd + t];        // coalesced global read
    for (int i = t; i < Nn * Nn; i += THREADS)
        adjs[i] = adj[i];
    for (int i = t; i < 3 * 2 * Fd; i += THREADS) {
        float v;
        if (i < 2 * Fd)            v = a1[i];
        else if (i < 4 * Fd)       v = a2[i - 2 * Fd];
        else                       v = ao[i - 4 * Fd];
        avs[i] = v;
    }
    __syncthreads();

    // ---- Phase 1: Wh1 = x@W1, Wh2 = x@W2 (thread t = output column t) ----
    {
        float acc1[Nn], acc2[Nn];
#pragma unroll
        for (int m = 0; m < Nn; m++) { acc1[m] = 0.0f; acc2[m] = 0.0f; }
        const float* W1p = W1 + t;
        const float* W2p = W2 + t;
#pragma unroll 4
        for (int k = 0; k < Fd; k++) {
            float w1 = W1p[k * Fd];
            float w2 = W2p[k * Fd];
            const float* xr = xs + k * NP;
#pragma unroll
            for (int i = 0; i < 5; i++) {
                float4 v = *(const float4*)(xr + 4 * i);
                acc1[4*i+0] += v.x * w1;  acc2[4*i+0] += v.x * w2;
                acc1[4*i+1] += v.y * w1;  acc2[4*i+1] += v.y * w2;
                acc1[4*i+2] += v.z * w1;  acc2[4*i+2] += v.z * w2;
                acc1[4*i+3] += v.w * w1;  acc2[4*i+3] += v.w * w2;
            }
            float2 v2 = *(const float2*)(xr + 20);
            acc1[20] += v2.x * w1;  acc2[20] += v2.x * w2;
            acc1[21] += v2.y * w1;  acc2[21] += v2.y * w2;
        }
#pragma unroll
        for (int m = 0; m < Nn; m++) {
            wh[m * Fd + t]                = acc1[m];
            wh[Nn * Fd + m * Fd + t]      = acc2[m];
        }
    }
    __syncthreads();

    // ---- Phase 2: e_src/e_dst per head (88 length-192 dots, staggered banks) ----
    if (t < 4 * Nn) {
        int which = t / Nn;                 // 0:e1s 1:e1d 2:e2s 3:e2d
        int m = t - which * Nn;
        const float* row = wh + (which >> 1) * (Nn * Fd) + m * Fd;
        const float* av  = avs + (which >> 1) * (2 * Fd) + (which & 1) * Fd;
        int kk = (t * 37) % Fd;
        float s = 0.0f;
        for (int k = 0; k < Fd; k++) {
            s += row[kk] * av[kk];
            kk++; if (kk == Fd) kk = 0;
        }
        ev[t] = s;
    }
    __syncthreads();

    // ---- Phase 3: softmax attention per head (44 rows) ----
    if (t < 2 * Nn) {
        int head = t / Nn, i = t - head * Nn;
        softmax_row(ev[head * 2 * Nn + i], ev + head * 2 * Nn + Nn,
                    adjs + i * Nn, att + head * (Nn * Nn) + i * Nn);
    }
    __syncthreads();

    // ---- Phase 4: h = elu(att @ Wh) -> hc transposed [384][24] ----
#pragma unroll
    for (int head = 0; head < 2; head++) {
        float hacc[Nn];
#pragma unroll
        for (int i = 0; i < Nn; i++) hacc[i] = 0.0f;
        const float* whh = wh + head * (Nn * Fd);
        const float* ah  = att + head * (Nn * Nn);
#pragma unroll 2
        for (int j = 0; j < Nn; j++) {
            float w = whh[j * Fd + t];
#pragma unroll
            for (int i = 0; i < Nn; i++)
                hacc[i] += ah[i * Nn + j] * w;
        }
        float* hcol = hc + (head * Fd + t) * NP;
#pragma unroll
        for (int i = 0; i < Nn; i++) {
            float v = hacc[i];
            v = (v > 0.0f) ? v : (expf(v) - 1.0f);    // elu
            hcol[i] = v;
        }
    }
    __syncthreads();

    // ---- Phase 5: Who = hcat @ Wo (K = 384); who aliases wh (wh now dead) ----
    {
        float acc[Nn];
#pragma unroll
        for (int m = 0; m < Nn; m++) acc[m] = 0.0f;
        const float* Wop = Wo + t;
#pragma unroll 4
        for (int k = 0; k < 2 * Fd; k++) {
            float w = Wop[k * Fd];
            const float* xr = hc + k * NP;
#pragma unroll
            for (int i = 0; i < 5; i++) {
                float4 v = *(const float4*)(xr + 4 * i);
                acc[4*i+0] += v.x * w;
                acc[4*i+1] += v.y * w;
                acc[4*i+2] += v.z * w;
                acc[4*i+3] += v.w * w;
            }
            float2 v2 = *(const float2*)(xr + 20);
            acc[20] += v2.x * w;
            acc[21] += v2.y * w;
        }
        __syncthreads();   // ensure all reads of wh finished before aliased write (wh dead since phase 4)
#pragma unroll
        for (int m = 0; m < Nn; m++) who[m * Fd + t] = acc[m];
    }
    __syncthreads();

    // ---- Phase 6: output-layer e vectors (44 dots) ----
    if (t < 2 * Nn) {
        int which = t / Nn;
        int m = t - which * Nn;
        const float* row = who + m * Fd;
        const float* av  = avs + 4 * Fd + which * Fd;   // ao
        int kk = (t * 37) % Fd;
        float s = 0.0f;
        for (int k = 0; k < Fd; k++) {
            s += row[kk] * av[kk];
            kk++; if (kk == Fd) kk = 0;
        }
        ev[88 + t] = s;
    }
    __syncthreads();

    // ---- Phase 7: output attention softmax (22 rows) ----
    if (t < Nn) {
        softmax_row(ev[88 + t], ev + 88 + Nn,
                    adjs + t * Nn, att + 2 * (Nn * Nn) + t * Nn);
    }
    __syncthreads();

    // ---- Phase 8: out = atto @ Who; y = elu(out) + x ----
    {
        float acc[Nn];
#pragma unroll
        for (int i = 0; i < Nn; i++) acc[i] = 0.0f;
        const float* ao_att = att + 2 * (Nn * Nn);
#pragma unroll 2
        for (int j = 0; j < Nn; j++) {
            float w = who[j * Fd + t];
#pragma unroll
            for (int i = 0; i < Nn; i++)
                acc[i] += ao_att[i * Nn + j] * w;
        }
        float* ob = out + b * (long long)(Nn * Fd);
#pragma unroll
        for (int m = 0; m < Nn; m++) {
            float v = acc[m];
            v = (v > 0.0f) ? v : (expf(v) - 1.0f);    // final elu
            ob[m * Fd + t] = v + xs[t * NP + m];      // residual, coalesced write
        }
    }
}

extern "C" void kernel_launch(void* const* d_in, const int* in_sizes, int n_in,
                              void* d_out, int out_size)
{
    const float* x   = (const float*)d_in[0];
    const float* adj = (const float*)d_in[1];
    const float* W1  = (const float*)d_in[2];
    const float* a1  = (const float*)d_in[3];
    const float* W2  = (const float*)d_in[4];
    const float* a2  = (const float*)d_in[5];
    const float* Wo  = (const float*)d_in[6];
    const float* ao  = (const float*)d_in[7];
    float* out = (float*)d_out;

    int b = in_sizes[0] / (Nn * Fd);

    cudaFuncSetAttribute(gat_fused, cudaFuncAttributeMaxDynamicSharedMemorySize, SMEM_BYTES);
    gat_fused<<<b, THREADS, SMEM_BYTES>>>(x, adj, W1, a1, W2, a2, Wo, ao, out);
}

// round 2
// speedup vs baseline: 1.1085x; 1.1085x over previous
#include <cuda_runtime.h>

#define Nn 22
#define NP 24          // padded node dim for float4-aligned SMEM rows
#define Fd 192
#define THREADS 192

// ---- SMEM layout (floats) ----
#define XS_OFF   0        // xs[k][m]: [192][24] transposed x tile
#define WH_OFF   4608     // wh[head][m][n]: [2][22][192]
#define WHO_OFF  WH_OFF   // who[m][n]: [22][192] (aliases wh, used after wh dead)
#define HC_OFF   13056    // hc[k][m]: [384][24] transposed hcat
#define ATT_OFF  22272    // attT[3][22][24]  (TRANSPOSED: attT[l][j*NP+i] = att_ij)
#define EV_OFF   23856    // e vectors: 132
#define ADJ_OFF  23988    // adj [484]
#define AV_OFF   24472    // a1(384) a2(384) ao(384)
#define SMEM_FLOATS 25624
#define SMEM_BYTES (SMEM_FLOATS * 4)

typedef unsigned long long u64;

__device__ __forceinline__ u64 pack2(float lo, float hi) {
    u64 r;
    asm("mov.b64 %0, {%1, %2};" : "=l"(r) : "f"(lo), "f"(hi));
    return r;
}
__device__ __forceinline__ void unpack2(u64 v, float& lo, float& hi) {
    asm("mov.b64 {%0, %1}, %2;" : "=f"(lo), "=f"(hi) : "l"(v));
}
// d += a * b, packed 2x fp32 (FFMA2 — only reachable via PTX)
__device__ __forceinline__ void fma2(u64& d, u64 a, u64 b) {
    asm("fma.rn.f32x2 %0, %1, %2, %0;" : "+l"(d) : "l"(a), "l"(b));
}

__device__ __forceinline__ float elu1(float v) {
    return (v > 0.0f) ? v : (__expf(v) - 1.0f);
}

// softmax over row i; writes TRANSPOSED into acol[j*NP] (column i of attT)
__device__ __forceinline__ void softmax_row(const float esrc, const float* __restrict__ edst,
                                            const float* __restrict__ adjrow,
                                            float* __restrict__ acol)
{
    float vals[Nn];
    float mx = -1e30f;
#pragma unroll
    for (int j = 0; j < Nn; j++) {
        if (adjrow[j] != 0.0f) {
            float v = esrc + edst[j];
            v = (v > 0.0f) ? v : 0.2f * v;   // LeakyReLU(0.2)
            vals[j] = v;
            mx = fmaxf(mx, v);
        } else {
            vals[j] = -1e30f;
        }
    }
    float ssum = 0.0f;
#pragma unroll
    for (int j = 0; j < Nn; j++) {
        float e = (vals[j] > -1e29f) ? __expf(vals[j] - mx) : 0.0f;
        vals[j] = e;
        ssum += e;
    }
    float inv = 1.0f / ssum;
#pragma unroll
    for (int j = 0; j < Nn; j++) acol[j * NP] = vals[j] * inv;
}

__global__ __launch_bounds__(THREADS, 2)
void gat_fused(const float* __restrict__ x, const float* __restrict__ adj,
               const float* __restrict__ W1, const float* __restrict__ a1,
               const float* __restrict__ W2, const float* __restrict__ a2,
               const float* __restrict__ Wo, const float* __restrict__ ao,
               float* __restrict__ out)
{
    extern __shared__ float sm[];
    float* xs   = sm + XS_OFF;
    float* wh   = sm + WH_OFF;
    float* who  = sm + WHO_OFF;
    float* hc   = sm + HC_OFF;
    float* attT = sm + ATT_OFF;
    float* ev   = sm + EV_OFF;
    float* adjs = sm + ADJ_OFF;
    float* avs  = sm + AV_OFF;

    const int t = threadIdx.x;
    const long long b = blockIdx.x;
    const float* xb = x + b * (long long)(Nn * Fd);

    // ---- Phase 0: load x (transposed), adj, a-vectors into SMEM ----
#pragma unroll
    for (int m = 0; m < Nn; m++)
        xs[t * NP + m] = xb[m * Fd + t];        // coalesced global read
    for (int i = t; i < Nn * Nn; i += THREADS)
        adjs[i] = adj[i];
    for (int i = t; i < 3 * 2 * Fd; i += THREADS) {
        float v;
        if (i < 2 * Fd)            v = a1[i];
        else if (i < 4 * Fd)       v = a2[i - 2 * Fd];
        else                       v = ao[i - 4 * Fd];
        avs[i] = v;
    }
    __syncthreads();

    // ---- Phase 1: Wh1 = x@W1, Wh2 = x@W2 (thread t = output column t) ----
    {
        u64 acc1[11], acc2[11];
#pragma unroll
        for (int p = 0; p < 11; p++) { acc1[p] = 0ull; acc2[p] = 0ull; }
        const float* W1p = W1 + t;
        const float* W2p = W2 + t;
#pragma unroll 4
        for (int k = 0; k < Fd; k++) {
            float w1 = W1p[k * Fd];
            float w2 = W2p[k * Fd];
            u64 w1p = pack2(w1, w1);
            u64 w2p = pack2(w2, w2);
            const u64* xr = (const u64*)(xs + k * NP);
#pragma unroll
            for (int p = 0; p < 11; p++) {
                u64 xv = xr[p];
                fma2(acc1[p], xv, w1p);
                fma2(acc2[p], xv, w2p);
            }
        }
#pragma unroll
        for (int p = 0; p < 11; p++) {
            float v0, v1;
            unpack2(acc1[p], v0, v1);
            wh[(2*p) * Fd + t]     = v0;
            wh[(2*p+1) * Fd + t]   = v1;
            unpack2(acc2[p], v0, v1);
            wh[Nn * Fd + (2*p) * Fd + t]   = v0;
            wh[Nn * Fd + (2*p+1) * Fd + t] = v1;
        }
    }
    __syncthreads();

    // ---- Phase 2: e_src/e_dst per head (88 length-192 dots, staggered banks) ----
    if (t < 4 * Nn) {
        int which = t / Nn;                 // 0:e1s 1:e1d 2:e2s 3:e2d
        int m = t - which * Nn;
        const float* row = wh + (which >> 1) * (Nn * Fd) + m * Fd;
        const float* av  = avs + (which >> 1) * (2 * Fd) + (which & 1) * Fd;
        int kk = (t * 37) % Fd;
        float s = 0.0f;
        for (int k = 0; k < Fd; k++) {
            s += row[kk] * av[kk];
            kk++; if (kk == Fd) kk = 0;
        }
        ev[t] = s;
    }
    __syncthreads();

    // ---- Phase 3: softmax attention per head (44 rows), TRANSPOSED write ----
    if (t < 2 * Nn) {
        int head = t / Nn, i = t - head * Nn;
        softmax_row(ev[head * 2 * Nn + i], ev + head * 2 * Nn + Nn,
                    adjs + i * Nn, attT + head * (Nn * NP) + i);
    }
    __syncthreads();

    // ---- Phase 4: h = elu(att @ Wh) -> hc transposed [384][24] ----
#pragma unroll
    for (int head = 0; head < 2; head++) {
        u64 hacc[11];
#pragma unroll
        for (int p = 0; p < 11; p++) hacc[p] = 0ull;
        const float* whh = wh + head * (Nn * Fd);
        const float* aT  = attT + head * (Nn * NP);
#pragma unroll 2
        for (int j = 0; j < Nn; j++) {
            float w = whh[j * Fd + t];
            u64 ww = pack2(w, w);
            const u64* ar = (const u64*)(aT + j * NP);   // pairs over i
#pragma unroll
            for (int p = 0; p < 11; p++)
                fma2(hacc[p], ar[p], ww);
        }
        float* hcol = hc + (head * Fd + t) * NP;
#pragma unroll
        for (int p = 0; p < 11; p++) {
            float v0, v1;
            unpack2(hacc[p], v0, v1);
            hcol[2*p]   = elu1(v0);
            hcol[2*p+1] = elu1(v1);
        }
    }
    __syncthreads();

    // ---- Phase 5: Who = hcat @ Wo (K = 384); who aliases wh (wh now dead) ----
    {
        u64 acc[11];
#pragma unroll
        for (int p = 0; p < 11; p++) acc[p] = 0ull;
        const float* Wop = Wo + t;
#pragma unroll 4
        for (int k = 0; k < 2 * Fd; k++) {
            float w = Wop[k * Fd];
            u64 ww = pack2(w, w);
            const u64* xr = (const u64*)(hc + k * NP);
#pragma unroll
            for (int p = 0; p < 11; p++)
                fma2(acc[p], xr[p], ww);
        }
        __syncthreads();   // all reads of wh finished before aliased write
#pragma unroll
        for (int p = 0; p < 11; p++) {
            float v0, v1;
            unpack2(acc[p], v0, v1);
            who[(2*p) * Fd + t]   = v0;
            who[(2*p+1) * Fd + t] = v1;
        }
    }
    __syncthreads();

    // ---- Phase 6: output-layer e vectors (44 dots) ----
    if (t < 2 * Nn) {
        int which = t / Nn;
        int m = t - which * Nn;
        const float* row = who + m * Fd;
        const float* av  = avs + 4 * Fd + which * Fd;   // ao
        int kk = (t * 37) % Fd;
        float s = 0.0f;
        for (int k = 0; k < Fd; k++) {
            s += row[kk] * av[kk];
            kk++; if (kk == Fd) kk = 0;
        }
        ev[88 + t] = s;
    }
    __syncthreads();

    // ---- Phase 7: output attention softmax (22 rows), TRANSPOSED write ----
    if (t < Nn) {
        softmax_row(ev[88 + t], ev + 88 + Nn,
                    adjs + t * Nn, attT + 2 * (Nn * NP) + t);
    }
    __syncthreads();

    // ---- Phase 8: out = atto @ Who; y = elu(out) + x ----
    {
        u64 acc[11];
#pragma unroll
        for (int p = 0; p < 11; p++) acc[p] = 0ull;
        const float* aT = attT + 2 * (Nn * NP);
#pragma unroll 2
        for (int j = 0; j < Nn; j++) {
            float w = who[j * Fd + t];
            u64 ww = pack2(w, w);
            const u64* ar = (const u64*)(aT + j * NP);
#pragma unroll
            for (int p = 0; p < 11; p++)
                fma2(acc[p], ar[p], ww);
        }
        float* ob = out + b * (long long)(Nn * Fd);
#pragma unroll
        for (int p = 0; p < 11; p++) {
            float v0, v1;
            unpack2(acc[p], v0, v1);
            int m0 = 2*p, m1 = 2*p+1;
            ob[m0 * Fd + t] = elu1(v0) + xs[t * NP + m0];   // residual
            ob[m1 * Fd + t] = elu1(v1) + xs[t * NP + m1];
        }
    }
}

extern "C" void kernel_launch(void* const* d_in, const int* in_sizes, int n_in,
                              void* d_out, int out_size)
{
    const float* x   = (const float*)d_in[0];
    const float* adj = (const float*)d_in[1];
    const float* W1  = (const float*)d_in[2];
    const float* a1  = (const float*)d_in[3];
    const float* W2  = (const float*)d_in[4];
    const float* a2  = (const float*)d_in[5];
    const float* Wo  = (const float*)d_in[6];
    const float* ao  = (const float*)d_in[7];
    float* out = (float*)d_out;

    int b = in_sizes[0] / (Nn * Fd);

    cudaFuncSetAttribute(gat_fused, cudaFuncAttributeMaxDynamicSharedMemorySize, SMEM_BYTES);
    gat_fused<<<b, THREADS, SMEM_BYTES>>>(x, adj, W1, a1, W2, a2, Wo, ao, out);
}